// round 10
// baseline (speedup 1.0000x reference)
#include <cuda_runtime.h>
#include <cstdint>

// BinaryLSTM: B=64, T=1024, D=128, H=512, C=2
// R10: 512 threads/CTA (4 warps/SMSP), k-halved gate partials + smem combine.
//      Sync/staging/xz/head frozen from R9 (single-variable experiment).

#define BB   64
#define TT   1024
#define DD   128
#define HH   512
#define G4   2048
#define NCLS 2
#define NCTA 128
#define NTHR 512
#define HROW 516      // h_s row stride (floats): 16B-mult, conflict-free
#define WTS  516      // weight stream stride

#define SMEM_FLOATS (BB*HROW + 16*WTS + 2048 + 8)
#define SMEM_BYTES  (SMEM_FLOATS * 4)

// xz pre-kernel (proven, unchanged)
#define XZ_TOK  32
#define XZ_COLS 256
#define XR      129
#define XZ_NTHR 256
#define XZ_SMEM_FLOATS (XZ_TOK*XR + DD*XZ_COLS)
#define XZ_SMEM_BYTES  (XZ_SMEM_FLOATS * 4)

typedef unsigned long long ull;

// ---- device scratch ----
__device__ float g_h[2][BB][HH];
__device__ float g_hs[(size_t)BB * TT * HH];
__device__ float g_xz[(size_t)BB * TT * G4];
__device__ unsigned g_sub[8 * 32];
__device__ unsigned g_root;
__device__ unsigned g_phase;

// ---- PTX helpers ----
__device__ __forceinline__ ull fma2(ull a, ull b, ull c) {
    ull d; asm("fma.rn.f32x2 %0, %1, %2, %3;" : "=l"(d) : "l"(a), "l"(b), "l"(c));
    return d;
}
__device__ __forceinline__ ull dup2(float x) {
    ull d; asm("mov.b64 %0, {%1, %1};" : "=l"(d) : "f"(x)); return d;
}
__device__ __forceinline__ ull pk2(float lo, float hi) {
    ull d; asm("mov.b64 %0, {%1, %2};" : "=l"(d) : "f"(lo), "f"(hi)); return d;
}
__device__ __forceinline__ float hadd2(ull v) {
    float lo, hi; asm("mov.b64 {%0, %1}, %2;" : "=f"(lo), "=f"(hi) : "l"(v));
    return lo + hi;
}
__device__ __forceinline__ uint32_t sa(const void* p) {
    return (uint32_t)__cvta_generic_to_shared(p);
}
__device__ __forceinline__ void cp16(uint32_t s, const void* g) {
    asm volatile("cp.async.cg.shared.global [%0], [%1], 16;" :: "r"(s), "l"(g));
}
#define CP_WAITALL() \
    asm volatile("cp.async.commit_group;\ncp.async.wait_group 0;" ::: "memory")

__device__ __forceinline__ unsigned atom_add_acqrel_gpu(unsigned* p, unsigned v) {
    unsigned old;
    asm volatile("atom.add.acq_rel.gpu.global.u32 %0, [%1], %2;"
                 : "=r"(old) : "l"(p), "r"(v) : "memory");
    return old;
}
__device__ __forceinline__ void st_release_gpu(unsigned* p, unsigned v) {
    asm volatile("st.release.gpu.global.u32 [%0], %1;" :: "l"(p), "r"(v) : "memory");
}
__device__ __forceinline__ unsigned ld_acquire_gpu(const unsigned* p) {
    unsigned v;
    asm volatile("ld.acquire.gpu.global.u32 %0, [%1];" : "=r"(v) : "l"(p) : "memory");
    return v;
}

// Two-level monotonic grid barrier (frozen from R9).
__device__ __forceinline__ void grid_barrier(unsigned target, int cta) {
    __syncthreads();
    if (threadIdx.x == 0) {
        unsigned grp = (unsigned)cta & 7u;
        unsigned old = atom_add_acqrel_gpu(&g_sub[grp * 32], 1u);
        if ((old & 15u) == 15u) {
            unsigned r = atom_add_acqrel_gpu(&g_root, 1u);
            if ((r & 7u) == 7u) st_release_gpu(&g_phase, target);
        }
        while ((int)(ld_acquire_gpu(&g_phase) - target) < 0) { }
    }
    __syncthreads();
}

__device__ __forceinline__ float fast_sigmoid(float z) {
    return 1.f / (1.f + __expf(-z));
}
__device__ __forceinline__ float fast_tanh(float z) {
    float az = fabsf(z);
    float e  = __expf(-2.f * az);
    float t  = (1.f - e) / (1.f + e);
    return copysignf(t, z);
}

// ---------------------------------------------------------------------------
// Pre-kernel (verbatim, proven): g_xz[token][col] = b[col] + x.Wx
// ---------------------------------------------------------------------------
__global__ void __launch_bounds__(XZ_NTHR, 1)
xz_kernel(const float* __restrict__ x,
          const float* __restrict__ Wx,
          const float* __restrict__ bias)
{
    extern __shared__ float sm[];
    float* x_s = sm;
    float* w_s = x_s + XZ_TOK * XR;

    const int tid  = threadIdx.x;
    const int tokT = blockIdx.x >> 3;
    const int colT = blockIdx.x & 7;
    const int cg   = tid >> 5;
    const int tt   = tid & 31;

    for (int c = tid; c < XZ_TOK * DD; c += XZ_NTHR) {
        int t = c >> 7, d = c & (DD - 1);
        int token = tokT * XZ_TOK + t;
        int bb = token & (BB - 1), s = token >> 6;
        x_s[t * XR + d] = x[((size_t)bb * TT + s) * DD + d];
    }
    const float* wg = Wx + colT * XZ_COLS;
    for (int c = tid; c < DD * XZ_COLS; c += XZ_NTHR) {
        int d = c >> 8, cl = c & 255;
        w_s[c] = wg[(size_t)d * G4 + cl];
    }
    __syncthreads();

    const int c0 = colT * XZ_COLS + cg * 32;
    ull acc[16];
    #pragma unroll
    for (int i = 0; i < 16; ++i) acc[i] = *(const ull*)(bias + c0 + 2 * i);

    const float* xr = x_s + tt * XR;
    const float* wr = w_s + cg * 32;
    #pragma unroll 4
    for (int d = 0; d < DD; ++d) {
        ull xd = dup2(xr[d]);
        const ulonglong2* w4 = (const ulonglong2*)(wr + d * XZ_COLS);
        #pragma unroll
        for (int i = 0; i < 8; ++i) {
            ulonglong2 w = w4[i];
            acc[2*i]   = fma2(xd, w.x, acc[2*i]);
            acc[2*i+1] = fma2(xd, w.y, acc[2*i+1]);
        }
    }
    int token = tokT * XZ_TOK + tt;
    ull* outp = (ull*)(g_xz + (size_t)token * G4 + c0);
    #pragma unroll
    for (int i = 0; i < 16; ++i) outp[i] = acc[i];
}

// ---------------------------------------------------------------------------
// Recurrence: 512 threads. tid = kh*256 + r; r = bb*4 + j.
// Thread (bb,j,kh) accumulates 4 gate partials of cell (bb, cta*4+j)
// over k in [kh*256, kh*256+256). Halves combined in smem; kh=0 does gates.
// ---------------------------------------------------------------------------
__global__ void __launch_bounds__(NTHR, 1)
lstm_persistent_kernel(const float* __restrict__ Wh,
                       float* __restrict__ d_cost)
{
    extern __shared__ float sm[];
    float* h_s  = sm;                 // [BB][HROW]
    float* whsT = h_s + BB * HROW;    // [16][WTS]  stream cc = g*4+j (full k)
    float* zs   = whsT + 16 * WTS;    // [256][8]   partials: [r][kh*4 + g]
    unsigned* pb = (unsigned*)(zs + 2048);

    const int tid = threadIdx.x;
    const int cta = blockIdx.x;
    const int kh  = tid >> 8;             // k-half
    const int r   = tid & 255;
    const int bb  = r >> 2;
    const int j   = r & 3;
    const int hc  = cta * 4 + j;
    const int k0  = kh << 8;              // 0 or 256

    if (cta == 0 && tid == 0) *d_cost = 0.f;

    // stationary K-major weight slice (16 streams x 512)
    for (int i = tid; i < 16 * HH; i += NTHR) {
        int cc = i >> 9, k = i & (HH - 1);
        int g = cc >> 2, jj = cc & 3;
        whsT[cc * WTS + k] = Wh[(size_t)k * G4 + g * HH + cta * 4 + jj];
    }
    if (tid == 0) *pb = ld_acquire_gpu(&g_phase);
    if (kh == 0) __stcg(&g_h[0][bb][hc], 0.f);
    __syncthreads();
    unsigned bar_t = *pb;

    grid_barrier(++bar_t, cta);           // h0 visible everywhere

    const float* hr = h_s + bb * HROW + k0;
    const float* w0 = whsT + (0 * 4 + j) * WTS + k0;
    const float* w1 = whsT + (1 * 4 + j) * WTS + k0;
    const float* w2 = whsT + (2 * 4 + j) * WTS + k0;
    const float* w3 = whsT + (3 * 4 + j) * WTS + k0;
    const size_t hs_base = (size_t)bb * TT * HH + hc;
    const size_t xz_off  = (size_t)cta * 4 + j;

    float c_state = 0.f;
    int cur = 0;
    for (int s = 0; s < TT; ++s) {
        // stage h -> smem (async, 16 chunks/thread, coalesced)
        const char* hg = (const char*)&g_h[cur][0][0];
        #pragma unroll
        for (int c = tid; c < 8192; c += NTHR) {
            int row = c >> 7, off = (c & 127) << 4;
            cp16(sa(h_s + row * HROW) + (unsigned)off, hg + row * (HH * 4) + off);
        }
        // xz pre-activations: only the kh=0 half seeds with xz (added once)
        float xzi = 0.f, xzf = 0.f, xzg = 0.f, xzo = 0.f;
        if (kh == 0) {
            const float* xzp = g_xz + ((size_t)s * BB + bb) * G4 + xz_off;
            xzi = __ldcg(xzp);
            xzf = __ldcg(xzp + HH);
            xzg = __ldcg(xzp + 2 * HH);
            xzo = __ldcg(xzp + 3 * HH);
        }
        CP_WAITALL();
        __syncthreads();

        ull a0 = pk2(xzi, 0.f), a1 = pk2(xzf, 0.f);
        ull a2 = pk2(xzg, 0.f), a3 = pk2(xzo, 0.f);

        #pragma unroll 4
        for (int k = 0; k < 256; k += 8) {
            ulonglong2 hA = *(const ulonglong2*)(hr + k);
            ulonglong2 hB = *(const ulonglong2*)(hr + k + 4);
            ulonglong2 wa, wb;
            wa = *(const ulonglong2*)(w0 + k); wb = *(const ulonglong2*)(w0 + k + 4);
            a0 = fma2(hA.x, wa.x, a0); a0 = fma2(hA.y, wa.y, a0);
            a0 = fma2(hB.x, wb.x, a0); a0 = fma2(hB.y, wb.y, a0);
            wa = *(const ulonglong2*)(w1 + k); wb = *(const ulonglong2*)(w1 + k + 4);
            a1 = fma2(hA.x, wa.x, a1); a1 = fma2(hA.y, wa.y, a1);
            a1 = fma2(hB.x, wb.x, a1); a1 = fma2(hB.y, wb.y, a1);
            wa = *(const ulonglong2*)(w2 + k); wb = *(const ulonglong2*)(w2 + k + 4);
            a2 = fma2(hA.x, wa.x, a2); a2 = fma2(hA.y, wa.y, a2);
            a2 = fma2(hB.x, wb.x, a2); a2 = fma2(hB.y, wb.y, a2);
            wa = *(const ulonglong2*)(w3 + k); wb = *(const ulonglong2*)(w3 + k + 4);
            a3 = fma2(hA.x, wa.x, a3); a3 = fma2(hA.y, wa.y, a3);
            a3 = fma2(hB.x, wb.x, a3); a3 = fma2(hB.y, wb.y, a3);
        }

        // partials -> smem: zs[r][kh*4 + g]
        *(float4*)(zs + r * 8 + kh * 4) =
            make_float4(hadd2(a0), hadd2(a1), hadd2(a2), hadd2(a3));
        __syncthreads();

        // gates on the kh=0 half (one thread per cell)
        if (kh == 0) {
            float4 p0 = *(const float4*)(zs + r * 8);
            float4 p1 = *(const float4*)(zs + r * 8 + 4);
            float zi = p0.x + p1.x, zf = p0.y + p1.y;
            float zg = p0.z + p1.z, zo = p0.w + p1.w;
            float ig = fast_sigmoid(zi), fg = fast_sigmoid(zf);
            float gg = fast_tanh(zg),    og = fast_sigmoid(zo);
            c_state  = fg * c_state + ig * gg;
            float hn = og * fast_tanh(c_state);
            __stcg(&g_h[cur ^ 1][bb][hc], hn);
            g_hs[hs_base + (size_t)s * HH] = hn;
        }

        grid_barrier(++bar_t, cta);
        cur ^= 1;
    }
}

// Head (verbatim, proven)
__global__ void __launch_bounds__(256)
head_kernel(const int* __restrict__ labels,
            const float* __restrict__ Wo,
            const float* __restrict__ bo,
            float* __restrict__ out,
            float* __restrict__ d_cost)
{
    __shared__ float part[8];
    int warp = threadIdx.x >> 5, lane = threadIdx.x & 31;
    int bt   = blockIdx.x * 8 + warp;
    const float* hrow = g_hs + (size_t)bt * HH;

    float s0 = 0.f, s1 = 0.f;
    #pragma unroll 4
    for (int k = lane; k < HH; k += 32) {
        float  h = hrow[k];
        float2 w = ((const float2*)Wo)[k];
        s0 += h * w.x; s1 += h * w.y;
    }
    #pragma unroll
    for (int off = 16; off; off >>= 1) {
        s0 += __shfl_xor_sync(0xffffffffu, s0, off);
        s1 += __shfl_xor_sync(0xffffffffu, s1, off);
    }
    if (lane == 0) {
        float l0 = s0 + bo[0], l1 = s1 + bo[1];
        float m  = fmaxf(l0, l1);
        float e0 = __expf(l0 - m), e1 = __expf(l1 - m);
        float Z  = e0 + e1;
        float inv = 1.f / Z;
        ((float2*)out)[bt] = make_float2(e0 * inv, e1 * inv);
        int lab = labels[bt];
        float llab = lab ? l1 : l0;
        part[warp] = -(llab - m - __logf(Z));
    }
    __syncthreads();
    if (threadIdx.x == 0) {
        float sum = 0.f;
        #pragma unroll
        for (int w = 0; w < 8; ++w) sum += part[w];
        atomicAdd(d_cost, sum * (1.f / (float)(BB * TT)));
    }
}

extern "C" void kernel_launch(void* const* d_in, const int* in_sizes, int n_in,
                              void* d_out, int out_size)
{
    (void)in_sizes; (void)n_in; (void)out_size;
    const float* x      = (const float*)d_in[0];
    const int*   labels = (const int*)  d_in[1];
    const float* Wx     = (const float*)d_in[2];
    const float* Wh     = (const float*)d_in[3];
    const float* b      = (const float*)d_in[4];
    const float* Wo     = (const float*)d_in[5];
    const float* bo     = (const float*)d_in[6];
    float* out    = (float*)d_out;
    float* d_cost = out + (size_t)BB * TT * NCLS;

    cudaFuncSetAttribute(xz_kernel,
                         cudaFuncAttributeMaxDynamicSharedMemorySize, XZ_SMEM_BYTES);
    cudaFuncSetAttribute(lstm_persistent_kernel,
                         cudaFuncAttributeMaxDynamicSharedMemorySize, SMEM_BYTES);

    xz_kernel<<<(BB * TT / XZ_TOK) * (G4 / XZ_COLS), XZ_NTHR, XZ_SMEM_BYTES>>>(x, Wx, b);
    lstm_persistent_kernel<<<NCTA, NTHR, SMEM_BYTES>>>(Wh, d_cost);
    head_kernel<<<(BB * TT) / 8, 256>>>(labels, Wo, bo, out, d_cost);
}

// round 12
// speedup vs baseline: 1.3797x; 1.3797x over previous
#include <cuda_runtime.h>
#include <cstdint>

// BinaryLSTM: B=64, T=1024, D=128, H=512, C=2
// R12: 3-kernel bisection. xz_kernel + head_kernel VERBATIM from R10 (proven).
// NEW: standalone group-recurrence — 4 independent batch groups x 32 CTAs,
// group-local barriers only, CTA = 16 h-cols x 16 group rows, cell per thread.

#define BB   64
#define TT   1024
#define DD   128
#define HH   512
#define G4   2048
#define NCLS 2
#define NCTA 128
#define NTHR 256
#define NGRP 4
#define GCTA 32       // CTAs per group
#define NBB  16       // batch rows per group
#define NJC  16       // h-cols per CTA
#define HROW 516      // h_s row stride (floats), 16B-mult
#define WTS  516      // weight stream stride

#define SMEM_FLOATS (NBB*HROW + 64*WTS + 8)
#define SMEM_BYTES  (SMEM_FLOATS * 4)

// xz pre-kernel (proven, unchanged)
#define XZ_TOK  32
#define XZ_COLS 256
#define XR      129
#define XZ_NTHR 256
#define XZ_SMEM_FLOATS (XZ_TOK*XR + DD*XZ_COLS)
#define XZ_SMEM_BYTES  (XZ_SMEM_FLOATS * 4)

typedef unsigned long long ull;

// ---- device scratch ----
__device__ float g_h[2][BB][HH];
__device__ float g_hs[(size_t)BB * TT * HH];
__device__ float g_xz[(size_t)BB * TT * G4];
__device__ unsigned g_gcnt[NGRP * 32];    // per-group arrive counters, 128B apart
__device__ unsigned g_gph [NGRP * 32];    // per-group phases, 128B apart

// ---- PTX helpers ----
__device__ __forceinline__ ull fma2(ull a, ull b, ull c) {
    ull d; asm("fma.rn.f32x2 %0, %1, %2, %3;" : "=l"(d) : "l"(a), "l"(b), "l"(c));
    return d;
}
__device__ __forceinline__ ull dup2(float x) {
    ull d; asm("mov.b64 %0, {%1, %1};" : "=l"(d) : "f"(x)); return d;
}
__device__ __forceinline__ ull pk2(float lo, float hi) {
    ull d; asm("mov.b64 %0, {%1, %2};" : "=l"(d) : "f"(lo), "f"(hi)); return d;
}
__device__ __forceinline__ float hadd2(ull v) {
    float lo, hi; asm("mov.b64 {%0, %1}, %2;" : "=f"(lo), "=f"(hi) : "l"(v));
    return lo + hi;
}
__device__ __forceinline__ uint32_t sa(const void* p) {
    return (uint32_t)__cvta_generic_to_shared(p);
}
__device__ __forceinline__ void cp16(uint32_t s, const void* g) {
    asm volatile("cp.async.cg.shared.global [%0], [%1], 16;" :: "r"(s), "l"(g));
}
#define CP_WAITALL() \
    asm volatile("cp.async.commit_group;\ncp.async.wait_group 0;" ::: "memory")

__device__ __forceinline__ unsigned atom_add_acqrel_gpu(unsigned* p, unsigned v) {
    unsigned old;
    asm volatile("atom.add.acq_rel.gpu.global.u32 %0, [%1], %2;"
                 : "=r"(old) : "l"(p), "r"(v) : "memory");
    return old;
}
__device__ __forceinline__ void st_release_gpu(unsigned* p, unsigned v) {
    asm volatile("st.release.gpu.global.u32 [%0], %1;" :: "l"(p), "r"(v) : "memory");
}
__device__ __forceinline__ unsigned ld_acquire_gpu(const unsigned* p) {
    unsigned v;
    asm volatile("ld.acquire.gpu.global.u32 %0, [%1];" : "=r"(v) : "l"(p) : "memory");
    return v;
}

// 32-CTA group barrier (monotonic phase, graph-replay-safe via captured base)
__device__ __forceinline__ void group_barrier(unsigned target, int grp) {
    __syncthreads();
    if (threadIdx.x == 0) {
        unsigned old = atom_add_acqrel_gpu(&g_gcnt[grp * 32], 1u);
        if ((old & (GCTA - 1u)) == GCTA - 1u)
            st_release_gpu(&g_gph[grp * 32], target);
        while ((int)(ld_acquire_gpu(&g_gph[grp * 32]) - target) < 0) { }
    }
    __syncthreads();
}

__device__ __forceinline__ float fast_sigmoid(float z) {
    return 1.f / (1.f + __expf(-z));
}
__device__ __forceinline__ float fast_tanh(float z) {
    float az = fabsf(z);
    float e  = __expf(-2.f * az);
    float t  = (1.f - e) / (1.f + e);
    return copysignf(t, z);
}

// ---------------------------------------------------------------------------
// Pre-kernel (VERBATIM from R10, proven): g_xz[token][col] = b[col] + x.Wx
// ---------------------------------------------------------------------------
__global__ void __launch_bounds__(XZ_NTHR, 1)
xz_kernel(const float* __restrict__ x,
          const float* __restrict__ Wx,
          const float* __restrict__ bias)
{
    extern __shared__ float sm[];
    float* x_s = sm;
    float* w_s = x_s + XZ_TOK * XR;

    const int tid  = threadIdx.x;
    const int tokT = blockIdx.x >> 3;
    const int colT = blockIdx.x & 7;
    const int cg   = tid >> 5;
    const int tt   = tid & 31;

    for (int c = tid; c < XZ_TOK * DD; c += XZ_NTHR) {
        int t = c >> 7, d = c & (DD - 1);
        int token = tokT * XZ_TOK + t;
        int bb = token & (BB - 1), s = token >> 6;
        x_s[t * XR + d] = x[((size_t)bb * TT + s) * DD + d];
    }
    const float* wg = Wx + colT * XZ_COLS;
    for (int c = tid; c < DD * XZ_COLS; c += XZ_NTHR) {
        int d = c >> 8, cl = c & 255;
        w_s[c] = wg[(size_t)d * G4 + cl];
    }
    __syncthreads();

    const int c0 = colT * XZ_COLS + cg * 32;
    ull acc[16];
    #pragma unroll
    for (int i = 0; i < 16; ++i) acc[i] = *(const ull*)(bias + c0 + 2 * i);

    const float* xr = x_s + tt * XR;
    const float* wr = w_s + cg * 32;
    #pragma unroll 4
    for (int d = 0; d < DD; ++d) {
        ull xd = dup2(xr[d]);
        const ulonglong2* w4 = (const ulonglong2*)(wr + d * XZ_COLS);
        #pragma unroll
        for (int i = 0; i < 8; ++i) {
            ulonglong2 w = w4[i];
            acc[2*i]   = fma2(xd, w.x, acc[2*i]);
            acc[2*i+1] = fma2(xd, w.y, acc[2*i+1]);
        }
    }
    int token = tokT * XZ_TOK + tt;
    ull* outp = (ull*)(g_xz + (size_t)token * G4 + c0);
    #pragma unroll
    for (int i = 0; i < 16; ++i) outp[i] = acc[i];
}

// ---------------------------------------------------------------------------
// Group recurrence: grid 128 = 4 groups x 32 CTAs. Group g owns batch rows
// [16g, 16g+16); CTA gc owns h-cols [16gc, 16gc+16). Thread (bb_l = tid&15,
// j = tid>>4) owns cell (bb, hc) and all 4 of its gates. Group-local sync only.
// ---------------------------------------------------------------------------
__global__ void __launch_bounds__(NTHR, 1)
group_lstm_kernel(const float* __restrict__ Wh,
                  float* __restrict__ d_cost)
{
    extern __shared__ float sm[];
    float* h_s  = sm;                 // [NBB][HROW] group's h rows
    float* whsT = sm + NBB * HROW;    // [64][WTS] stream cc = g*16 + jj
    unsigned* pb = (unsigned*)(whsT + 64 * WTS);

    const int tid  = threadIdx.x;
    const int cta  = blockIdx.x;
    const int grp  = cta >> 5;
    const int gc   = cta & 31;
    const int bb_l = tid & 15;
    const int j    = tid >> 4;
    const int bb   = grp * NBB + bb_l;
    const int hc   = gc * NJC + j;

    if (cta == 0 && tid == 0) *d_cost = 0.f;

    // stationary weights: stream (g, jj) = Wh[k][g*HH + gc*16 + jj], K-major
    for (int i = tid; i < 64 * HH; i += NTHR) {
        int cc = i >> 9, k = i & (HH - 1);
        whsT[cc * WTS + k] = Wh[(size_t)k * G4 + (cc >> 4) * HH + gc * NJC + (cc & 15)];
    }
    if (tid == 0) *pb = ld_acquire_gpu(&g_gph[grp * 32]);
    __stcg(&g_h[0][bb][hc], 0.f);
    __syncthreads();
    unsigned gb_t = *pb;

    group_barrier(++gb_t, grp);           // group's h0 visible group-wide

    const float* hr = h_s + bb_l * HROW;
    const float* w0 = whsT + (0 * NJC + j) * WTS;
    const float* w1 = whsT + (1 * NJC + j) * WTS;
    const float* w2 = whsT + (2 * NJC + j) * WTS;
    const float* w3 = whsT + (3 * NJC + j) * WTS;
    const size_t hs_base = (size_t)bb * TT * HH + hc;

    float c_state = 0.f;
    int cur = 0;
    for (int s = 0; s < TT; ++s) {
        // stage the group's 16 h rows (32 KB), 8 chunks/thread
        const char* hg = (const char*)&g_h[cur][grp * NBB][0];
        #pragma unroll
        for (int c = tid; c < 2048; c += NTHR) {
            int row = c >> 7, off = (c & 127) << 4;
            cp16(sa(h_s + row * HROW) + (unsigned)off, hg + row * (HH * 4) + off);
        }
        const float* xzp = g_xz + ((size_t)s * BB + bb) * G4 + hc;
        float xzi = __ldcg(xzp);
        float xzf = __ldcg(xzp + HH);
        float xzg = __ldcg(xzp + 2 * HH);
        float xzo = __ldcg(xzp + 3 * HH);
        CP_WAITALL();
        __syncthreads();

        ull a0 = pk2(xzi, 0.f), a1 = pk2(xzf, 0.f);
        ull a2 = pk2(xzg, 0.f), a3 = pk2(xzo, 0.f);
        #pragma unroll 4
        for (int k = 0; k < HH; k += 8) {
            ulonglong2 hA = *(const ulonglong2*)(hr + k);
            ulonglong2 hB = *(const ulonglong2*)(hr + k + 4);
            ulonglong2 wa, wb;
            wa = *(const ulonglong2*)(w0 + k); wb = *(const ulonglong2*)(w0 + k + 4);
            a0 = fma2(hA.x, wa.x, a0); a0 = fma2(hA.y, wa.y, a0);
            a0 = fma2(hB.x, wb.x, a0); a0 = fma2(hB.y, wb.y, a0);
            wa = *(const ulonglong2*)(w1 + k); wb = *(const ulonglong2*)(w1 + k + 4);
            a1 = fma2(hA.x, wa.x, a1); a1 = fma2(hA.y, wa.y, a1);
            a1 = fma2(hB.x, wb.x, a1); a1 = fma2(hB.y, wb.y, a1);
            wa = *(const ulonglong2*)(w2 + k); wb = *(const ulonglong2*)(w2 + k + 4);
            a2 = fma2(hA.x, wa.x, a2); a2 = fma2(hA.y, wa.y, a2);
            a2 = fma2(hB.x, wb.x, a2); a2 = fma2(hB.y, wb.y, a2);
            wa = *(const ulonglong2*)(w3 + k); wb = *(const ulonglong2*)(w3 + k + 4);
            a3 = fma2(hA.x, wa.x, a3); a3 = fma2(hA.y, wa.y, a3);
            a3 = fma2(hB.x, wb.x, a3); a3 = fma2(hB.y, wb.y, a3);
        }

        float zi = hadd2(a0), zf = hadd2(a1), zg = hadd2(a2), zo = hadd2(a3);
        float ig = fast_sigmoid(zi), fg = fast_sigmoid(zf);
        float gg = fast_tanh(zg),    og = fast_sigmoid(zo);
        c_state  = fg * c_state + ig * gg;
        float hn = og * fast_tanh(c_state);
        __stcg(&g_h[cur ^ 1][bb][hc], hn);
        __stcg(&g_hs[hs_base + (size_t)s * HH], hn);

        group_barrier(++gb_t, grp);
        cur ^= 1;
    }
}

// Head (VERBATIM from R10, proven)
__global__ void __launch_bounds__(256)
head_kernel(const int* __restrict__ labels,
            const float* __restrict__ Wo,
            const float* __restrict__ bo,
            float* __restrict__ out,
            float* __restrict__ d_cost)
{
    __shared__ float part[8];
    int warp = threadIdx.x >> 5, lane = threadIdx.x & 31;
    int bt   = blockIdx.x * 8 + warp;
    const float* hrow = g_hs + (size_t)bt * HH;

    float s0 = 0.f, s1 = 0.f;
    #pragma unroll 4
    for (int k = lane; k < HH; k += 32) {
        float  h = hrow[k];
        float2 w = ((const float2*)Wo)[k];
        s0 += h * w.x; s1 += h * w.y;
    }
    #pragma unroll
    for (int off = 16; off; off >>= 1) {
        s0 += __shfl_xor_sync(0xffffffffu, s0, off);
        s1 += __shfl_xor_sync(0xffffffffu, s1, off);
    }
    if (lane == 0) {
        float l0 = s0 + bo[0], l1 = s1 + bo[1];
        float m  = fmaxf(l0, l1);
        float e0 = __expf(l0 - m), e1 = __expf(l1 - m);
        float Z  = e0 + e1;
        float inv = 1.f / Z;
        ((float2*)out)[bt] = make_float2(e0 * inv, e1 * inv);
        int lab = labels[bt];
        float llab = lab ? l1 : l0;
        part[warp] = -(llab - m - __logf(Z));
    }
    __syncthreads();
    if (threadIdx.x == 0) {
        float sum = 0.f;
        #pragma unroll
        for (int w = 0; w < 8; ++w) sum += part[w];
        atomicAdd(d_cost, sum * (1.f / (float)(BB * TT)));
    }
}

extern "C" void kernel_launch(void* const* d_in, const int* in_sizes, int n_in,
                              void* d_out, int out_size)
{
    (void)in_sizes; (void)n_in; (void)out_size;
    const float* x      = (const float*)d_in[0];
    const int*   labels = (const int*)  d_in[1];
    const float* Wx     = (const float*)d_in[2];
    const float* Wh     = (const float*)d_in[3];
    const float* b      = (const float*)d_in[4];
    const float* Wo     = (const float*)d_in[5];
    const float* bo     = (const float*)d_in[6];
    float* out    = (float*)d_out;
    float* d_cost = out + (size_t)BB * TT * NCLS;

    cudaFuncSetAttribute(xz_kernel,
                         cudaFuncAttributeMaxDynamicSharedMemorySize, XZ_SMEM_BYTES);
    cudaFuncSetAttribute(group_lstm_kernel,
                         cudaFuncAttributeMaxDynamicSharedMemorySize, SMEM_BYTES);

    xz_kernel<<<(BB * TT / XZ_TOK) * (G4 / XZ_COLS), XZ_NTHR, XZ_SMEM_BYTES>>>(x, Wx, b);
    group_lstm_kernel<<<NCTA, NTHR, SMEM_BYTES>>>(Wh, d_cost);
    head_kernel<<<(BB * TT) / 8, 256>>>(labels, Wo, bo, out, d_cost);
}

// round 14
// speedup vs baseline: 1.5480x; 1.1219x over previous
#include <cuda_runtime.h>
#include <cstdint>

// BinaryLSTM: B=64, T=1024, D=128, H=512, C=2
// R13 = R12 (proven) + L1tex-wavefront elimination:
//   1) h staging via cp.async.bulk (TMA 1D) + mbarrier (was 2048x cp.async.cg)
//   2) xz in float4 layout [s][hc][bb][ifgo] -> 1 coalesced LDG.128 per cell
//   3) h/g_hs writeback through smem transpose tile -> coalesced 64B stores

#define BB   64
#define TT   1024
#define DD   128
#define HH   512
#define G4   2048
#define NCLS 2
#define NCTA 128
#define NTHR 256
#define NGRP 4
#define GCTA 32
#define NBB  16
#define NJC  16
#define HROW 516
#define WTS  516

// smem layout (float offsets)
#define W_OFF    (NBB*HROW)              // 8256
#define HOUT_OFF (W_OFF + 64*WTS)        // 41280
#define MBAR_OFF (HOUT_OFF + 272)        // 41552 (byte 166208, 8-aligned)
#define PB_OFF   (MBAR_OFF + 2)
#define SMEM_FLOATS (PB_OFF + 2)
#define SMEM_BYTES  (SMEM_FLOATS * 4)

// xz kernel
#define XZ_TOK  32
#define XR      129
#define XZ_NTHR 256
#define XZ_SMEM_FLOATS (XZ_TOK*XR + DD*256)
#define XZ_SMEM_BYTES  (XZ_SMEM_FLOATS * 4)

typedef unsigned long long ull;

// ---- device scratch ----
__device__ float  g_h[2][BB][HH];
__device__ float  g_hs[(size_t)BB * TT * HH];
__device__ float4 g_xz4[(size_t)BB * TT * HH];   // [s][hc][bb] -> (i,f,g,o)
__device__ unsigned g_gcnt[NGRP * 32];
__device__ unsigned g_gph [NGRP * 32];

// ---- PTX helpers ----
__device__ __forceinline__ ull fma2(ull a, ull b, ull c) {
    ull d; asm("fma.rn.f32x2 %0, %1, %2, %3;" : "=l"(d) : "l"(a), "l"(b), "l"(c));
    return d;
}
__device__ __forceinline__ ull dup2(float x) {
    ull d; asm("mov.b64 %0, {%1, %1};" : "=l"(d) : "f"(x)); return d;
}
__device__ __forceinline__ ull pk2(float lo, float hi) {
    ull d; asm("mov.b64 %0, {%1, %2};" : "=l"(d) : "f"(lo), "f"(hi)); return d;
}
__device__ __forceinline__ float hadd2(ull v) {
    float lo, hi; asm("mov.b64 {%0, %1}, %2;" : "=f"(lo), "=f"(hi) : "l"(v));
    return lo + hi;
}
__device__ __forceinline__ uint32_t sa(const void* p) {
    return (uint32_t)__cvta_generic_to_shared(p);
}
__device__ __forceinline__ void mbar_wait(uint32_t mbar, unsigned parity) {
    asm volatile(
        "{\n\t.reg .pred P1;\n\t"
        "WAIT_%=:\n\t"
        "mbarrier.try_wait.parity.acquire.cta.shared::cta.b64 P1, [%0], %1;\n\t"
        "@P1 bra.uni DONE_%=;\n\t"
        "bra.uni WAIT_%=;\n\t"
        "DONE_%=:\n\t}"
        :: "r"(mbar), "r"(parity) : "memory");
}

__device__ __forceinline__ unsigned atom_add_acqrel_gpu(unsigned* p, unsigned v) {
    unsigned old;
    asm volatile("atom.add.acq_rel.gpu.global.u32 %0, [%1], %2;"
                 : "=r"(old) : "l"(p), "r"(v) : "memory");
    return old;
}
__device__ __forceinline__ void st_release_gpu(unsigned* p, unsigned v) {
    asm volatile("st.release.gpu.global.u32 [%0], %1;" :: "l"(p), "r"(v) : "memory");
}
__device__ __forceinline__ unsigned ld_acquire_gpu(const unsigned* p) {
    unsigned v;
    asm volatile("ld.acquire.gpu.global.u32 %0, [%1];" : "=r"(v) : "l"(p) : "memory");
    return v;
}

// 32-CTA group barrier (frozen, proven in R12)
__device__ __forceinline__ void group_barrier(unsigned target, int grp) {
    __syncthreads();
    if (threadIdx.x == 0) {
        unsigned old = atom_add_acqrel_gpu(&g_gcnt[grp * 32], 1u);
        if ((old & (GCTA - 1u)) == GCTA - 1u)
            st_release_gpu(&g_gph[grp * 32], target);
        while ((int)(ld_acquire_gpu(&g_gph[grp * 32]) - target) < 0) { }
    }
    __syncthreads();
}

__device__ __forceinline__ float fast_sigmoid(float z) {
    return 1.f / (1.f + __expf(-z));
}
__device__ __forceinline__ float fast_tanh(float z) {
    float az = fabsf(z);
    float e  = __expf(-2.f * az);
    float t  = (1.f - e) / (1.f + e);
    return copysignf(t, z);
}

// ---------------------------------------------------------------------------
// xz kernel: thread owns (token, 8 hc x 4 gates); writes coalesced float4s.
// Per-column accumulation is in d-order (identical rounding to R12).
// ---------------------------------------------------------------------------
__global__ void __launch_bounds__(XZ_NTHR, 1)
xz_kernel(const float* __restrict__ x,
          const float* __restrict__ Wx,
          const float* __restrict__ bias)
{
    extern __shared__ float sm[];
    float* x_s = sm;                  // [32][129]
    float* w_s = sm + XZ_TOK * XR;    // [128][256], col cl = g*64 + hcl

    const int tid  = threadIdx.x;
    const int tokT = blockIdx.x >> 3;
    const int colT = blockIdx.x & 7;           // 64-hc tile
    const int cg   = tid >> 5;                 // warp = 8 hc
    const int tt   = tid & 31;                 // lane = token

    for (int c = tid; c < XZ_TOK * DD; c += XZ_NTHR) {
        int t = c >> 7, d = c & (DD - 1);
        int token = tokT * XZ_TOK + t;
        int bb = token & (BB - 1), s = token >> 6;
        x_s[t * XR + d] = x[((size_t)bb * TT + s) * DD + d];
    }
    for (int c = tid; c < DD * 256; c += XZ_NTHR) {
        int d = c >> 8, cl = c & 255;
        w_s[c] = Wx[(size_t)d * G4 + (cl >> 6) * HH + colT * 64 + (cl & 63)];
    }
    __syncthreads();

    const int hc0 = colT * 64 + cg * 8;
    ull acc[4][4];
    #pragma unroll
    for (int g = 0; g < 4; ++g)
        #pragma unroll
        for (int p = 0; p < 4; ++p)
            acc[g][p] = *(const ull*)(bias + g * HH + hc0 + 2 * p);

    const float* xr = x_s + tt * XR;
    #pragma unroll 4
    for (int d = 0; d < DD; ++d) {
        ull xd = dup2(xr[d]);
        const ull* wr = (const ull*)(w_s + d * 256 + cg * 8);
        #pragma unroll
        for (int g = 0; g < 4; ++g) {
            const ull* wg2 = wr + g * 32;     // +64 floats per gate
            acc[g][0] = fma2(xd, wg2[0], acc[g][0]);
            acc[g][1] = fma2(xd, wg2[1], acc[g][1]);
            acc[g][2] = fma2(xd, wg2[2], acc[g][2]);
            acc[g][3] = fma2(xd, wg2[3], acc[g][3]);
        }
    }
    int token = tokT * XZ_TOK + tt;
    int bb = token & (BB - 1), s = token >> 6;
    float v[4][8];
    #pragma unroll
    for (int g = 0; g < 4; ++g)
        #pragma unroll
        for (int p = 0; p < 4; ++p) {
            float lo, hi;
            asm("mov.b64 {%0, %1}, %2;" : "=f"(lo), "=f"(hi) : "l"(acc[g][p]));
            v[g][2 * p] = lo; v[g][2 * p + 1] = hi;
        }
    #pragma unroll
    for (int ii = 0; ii < 8; ++ii)             // lanes bb-consecutive: 512B runs
        g_xz4[((size_t)s * HH + hc0 + ii) * BB + bb] =
            make_float4(v[0][ii], v[1][ii], v[2][ii], v[3][ii]);
}

// ---------------------------------------------------------------------------
// Group recurrence (R12 structure; staging/xz-read/writeback replaced)
// ---------------------------------------------------------------------------
__global__ void __launch_bounds__(NTHR, 1)
group_lstm_kernel(const float* __restrict__ Wh,
                  float* __restrict__ d_cost)
{
    extern __shared__ float sm[];
    float* h_s  = sm;                          // [NBB][HROW]
    float* whsT = sm + W_OFF;                  // [64][WTS]
    float* hout = sm + HOUT_OFF;               // [16][17] transpose tile
    const uint32_t mbar = sa(sm + MBAR_OFF);
    unsigned* pb = (unsigned*)(sm + PB_OFF);

    const int tid  = threadIdx.x;
    const int cta  = blockIdx.x;
    const int grp  = cta >> 5;
    const int gc   = cta & 31;
    const int bb_l = tid & 15;
    const int j    = tid >> 4;
    const int bb   = grp * NBB + bb_l;
    const int hc   = gc * NJC + j;

    if (cta == 0 && tid == 0) *d_cost = 0.f;

    for (int i = tid; i < 64 * HH; i += NTHR) {
        int cc = i >> 9, k = i & (HH - 1);
        whsT[cc * WTS + k] = Wh[(size_t)k * G4 + (cc >> 4) * HH + gc * NJC + (cc & 15)];
    }
    if (tid == 0) {
        *pb = ld_acquire_gpu(&g_gph[grp * 32]);
        asm volatile("mbarrier.init.shared.b64 [%0], %1;" :: "r"(mbar), "r"(1u) : "memory");
    }
    __stcg(&g_h[0][bb][hc], 0.f);
    __syncthreads();
    unsigned gb_t = *pb;

    group_barrier(++gb_t, grp);               // group h0 visible

    const float* hr = h_s + bb_l * HROW;
    const float* w0 = whsT + (0 * NJC + j) * WTS;
    const float* w1 = whsT + (1 * NJC + j) * WTS;
    const float* w2 = whsT + (2 * NJC + j) * WTS;
    const float* w3 = whsT + (3 * NJC + j) * WTS;
    const uint32_t hs_a = sa(h_s);

    float c_state = 0.f;
    int cur = 0;
    for (int s = 0; s < TT; ++s) {
        // ---- bulk-async stage of the group's 16 h rows (32 KB total) ----
        if (tid == 0) {
            asm volatile("mbarrier.arrive.expect_tx.shared.b64 _, [%0], %1;"
                         :: "r"(mbar), "r"(32768u) : "memory");
            const char* hg = (const char*)&g_h[cur][grp * NBB][0];
            #pragma unroll
            for (int rr = 0; rr < NBB; ++rr)
                asm volatile(
                    "cp.async.bulk.shared::cta.global.mbarrier::complete_tx::bytes "
                    "[%0], [%1], %2, [%3];"
                    :: "r"(hs_a + (unsigned)(rr * HROW * 4)),
                       "l"(hg + rr * (HH * 4)), "r"(2048u), "r"(mbar) : "memory");
        }
        // coalesced xz read (independent of staging; overlaps the wait)
        float4 xzv = g_xz4[((size_t)s * HH + hc) * BB + bb];
        mbar_wait(mbar, (unsigned)(s & 1));

        ull a0 = pk2(xzv.x, 0.f), a1 = pk2(xzv.y, 0.f);
        ull a2 = pk2(xzv.z, 0.f), a3 = pk2(xzv.w, 0.f);
        #pragma unroll 4
        for (int k = 0; k < HH; k += 8) {
            ulonglong2 hA = *(const ulonglong2*)(hr + k);
            ulonglong2 hB = *(const ulonglong2*)(hr + k + 4);
            ulonglong2 wa, wb;
            wa = *(const ulonglong2*)(w0 + k); wb = *(const ulonglong2*)(w0 + k + 4);
            a0 = fma2(hA.x, wa.x, a0); a0 = fma2(hA.y, wa.y, a0);
            a0 = fma2(hB.x, wb.x, a0); a0 = fma2(hB.y, wb.y, a0);
            wa = *(const ulonglong2*)(w1 + k); wb = *(const ulonglong2*)(w1 + k + 4);
            a1 = fma2(hA.x, wa.x, a1); a1 = fma2(hA.y, wa.y, a1);
            a1 = fma2(hB.x, wb.x, a1); a1 = fma2(hB.y, wb.y, a1);
            wa = *(const ulonglong2*)(w2 + k); wb = *(const ulonglong2*)(w2 + k + 4);
            a2 = fma2(hA.x, wa.x, a2); a2 = fma2(hA.y, wa.y, a2);
            a2 = fma2(hB.x, wb.x, a2); a2 = fma2(hB.y, wb.y, a2);
            wa = *(const ulonglong2*)(w3 + k); wb = *(const ulonglong2*)(w3 + k + 4);
            a3 = fma2(hA.x, wa.x, a3); a3 = fma2(hA.y, wa.y, a3);
            a3 = fma2(hB.x, wb.x, a3); a3 = fma2(hB.y, wb.y, a3);
        }

        float zi = hadd2(a0), zf = hadd2(a1), zg = hadd2(a2), zo = hadd2(a3);
        float ig = fast_sigmoid(zi), fg = fast_sigmoid(zf);
        float gg = fast_tanh(zg),    og = fast_sigmoid(zo);
        c_state  = fg * c_state + ig * gg;
        float hn = og * fast_tanh(c_state);

        // ---- coalesced writeback via smem transpose tile ----
        hout[bb_l * 17 + j] = hn;
        __syncthreads();
        {
            int b2 = tid >> 4, h2 = tid & 15;           // lanes: h2 fast -> 64B runs
            float val = hout[b2 * 17 + h2];
            __stcg(&g_h[cur ^ 1][grp * NBB + b2][gc * NJC + h2], val);
            g_hs[((size_t)(grp * NBB + b2) * TT + s) * HH + gc * NJC + h2] = val;
        }

        group_barrier(++gb_t, grp);
        cur ^= 1;
    }
}

// Head (VERBATIM, proven)
__global__ void __launch_bounds__(256)
head_kernel(const int* __restrict__ labels,
            const float* __restrict__ Wo,
            const float* __restrict__ bo,
            float* __restrict__ out,
            float* __restrict__ d_cost)
{
    __shared__ float part[8];
    int warp = threadIdx.x >> 5, lane = threadIdx.x & 31;
    int bt   = blockIdx.x * 8 + warp;
    const float* hrow = g_hs + (size_t)bt * HH;

    float s0 = 0.f, s1 = 0.f;
    #pragma unroll 4
    for (int k = lane; k < HH; k += 32) {
        float  h = hrow[k];
        float2 w = ((const float2*)Wo)[k];
        s0 += h * w.x; s1 += h * w.y;
    }
    #pragma unroll
    for (int off = 16; off; off >>= 1) {
        s0 += __shfl_xor_sync(0xffffffffu, s0, off);
        s1 += __shfl_xor_sync(0xffffffffu, s1, off);
    }
    if (lane == 0) {
        float l0 = s0 + bo[0], l1 = s1 + bo[1];
        float m  = fmaxf(l0, l1);
        float e0 = __expf(l0 - m), e1 = __expf(l1 - m);
        float Z  = e0 + e1;
        float inv = 1.f / Z;
        ((float2*)out)[bt] = make_float2(e0 * inv, e1 * inv);
        int lab = labels[bt];
        float llab = lab ? l1 : l0;
        part[warp] = -(llab - m - __logf(Z));
    }
    __syncthreads();
    if (threadIdx.x == 0) {
        float sum = 0.f;
        #pragma unroll
        for (int w = 0; w < 8; ++w) sum += part[w];
        atomicAdd(d_cost, sum * (1.f / (float)(BB * TT)));
    }
}

extern "C" void kernel_launch(void* const* d_in, const int* in_sizes, int n_in,
                              void* d_out, int out_size)
{
    (void)in_sizes; (void)n_in; (void)out_size;
    const float* x      = (const float*)d_in[0];
    const int*   labels = (const int*)  d_in[1];
    const float* Wx     = (const float*)d_in[2];
    const float* Wh     = (const float*)d_in[3];
    const float* b      = (const float*)d_in[4];
    const float* Wo     = (const float*)d_in[5];
    const float* bo     = (const float*)d_in[6];
    float* out    = (float*)d_out;
    float* d_cost = out + (size_t)BB * TT * NCLS;

    cudaFuncSetAttribute(xz_kernel,
                         cudaFuncAttributeMaxDynamicSharedMemorySize, XZ_SMEM_BYTES);
    cudaFuncSetAttribute(group_lstm_kernel,
                         cudaFuncAttributeMaxDynamicSharedMemorySize, SMEM_BYTES);

    xz_kernel<<<(BB * TT / XZ_TOK) * 8, XZ_NTHR, XZ_SMEM_BYTES>>>(x, Wx, b);
    group_lstm_kernel<<<NCTA, NTHR, SMEM_BYTES>>>(Wh, d_cost);
    head_kernel<<<(BB * TT) / 8, 256>>>(labels, Wo, bo, out, d_cost);
}